// round 1
// baseline (speedup 1.0000x reference)
#include <cuda_runtime.h>
#include <cuda_bf16.h>
#include <math.h>

#define B_ 4
#define C_ 96
#define H_ 256
#define W_ 256
#define HW (H_*W_)
#define NPIX (B_*HW)

// Scratch (allocation-free rule: __device__ globals)
__device__ float g_xn[B_*C_*HW];   // layernorm output
__device__ float g_buf[B_*C_*HW];  // e0_pre, later reused for x1
__device__ float g_xa[B_*C_*HW];   // x_adaptive

// ---------------------------------------------------------------------------
// Kernel 1: per-pixel LayerNorm over C, then e0 pointwise 1x1 (96x96 matvec)
// One thread = one pixel. Channel vector kept in registers.
// ---------------------------------------------------------------------------
__global__ __launch_bounds__(256) void k_ln_e0pw(
    const float* __restrict__ x,
    const float* __restrict__ lnw, const float* __restrict__ lnb,
    const float* __restrict__ w,  const float* __restrict__ bias)
{
    __shared__ float ws[C_*C_];
    __shared__ float bs[C_], lws[C_], lbs[C_];
    for (int i = threadIdx.x; i < (C_*C_)/4; i += 256)
        reinterpret_cast<float4*>(ws)[i] = reinterpret_cast<const float4*>(w)[i];
    if (threadIdx.x < C_) {
        bs[threadIdx.x]  = bias[threadIdx.x];
        lws[threadIdx.x] = lnw[threadIdx.x];
        lbs[threadIdx.x] = lnb[threadIdx.x];
    }
    __syncthreads();

    int b = blockIdx.y;
    int p = blockIdx.x * 256 + threadIdx.x;
    const float* xb = x + (size_t)b * C_ * HW + p;

    float xr[C_];
    float mean = 0.f;
    #pragma unroll
    for (int c = 0; c < C_; c++) { xr[c] = xb[(size_t)c * HW]; mean += xr[c]; }
    mean *= (1.f / C_);
    float var = 0.f;
    #pragma unroll
    for (int c = 0; c < C_; c++) { float d = xr[c] - mean; var += d * d; }
    var *= (1.f / C_);
    float inv = rsqrtf(var + 1e-6f);
    #pragma unroll
    for (int c = 0; c < C_; c++)
        xr[c] = (xr[c] - mean) * inv * lws[c] + lbs[c];

    float* xnb = g_xn + (size_t)b * C_ * HW + p;
    #pragma unroll
    for (int c = 0; c < C_; c++) xnb[(size_t)c * HW] = xr[c];

    float* eb = g_buf + (size_t)b * C_ * HW + p;
    #pragma unroll 1
    for (int o = 0; o < C_; o++) {
        const float4* wrow = reinterpret_cast<const float4*>(&ws[o * C_]);
        float a0 = 0.f, a1 = 0.f, a2 = 0.f, a3 = 0.f;
        #pragma unroll
        for (int c4 = 0; c4 < C_/4; c4++) {
            float4 wv = wrow[c4];
            a0 += wv.x * xr[4*c4 + 0];
            a1 += wv.y * xr[4*c4 + 1];
            a2 += wv.z * xr[4*c4 + 2];
            a3 += wv.w * xr[4*c4 + 3];
        }
        eb[(size_t)o * HW] = bs[o] + ((a0 + a1) + (a2 + a3));
    }
}

// ---------------------------------------------------------------------------
// Kernel 2: three depthwise convs + soft mixing + prompt scaling
// Block = one (b, c, 32x32 tile). Halo 6 for dil-3 5x5; halo 1 for e0_pre.
// ---------------------------------------------------------------------------
#define TS 32
__global__ __launch_bounds__(256) void k_dw(
    const float* __restrict__ sw,     // [B,3]
    const float* __restrict__ prompt, // [B,C]
    const float* __restrict__ w0, const float* __restrict__ b0,
    const float* __restrict__ w1, const float* __restrict__ b1,
    const float* __restrict__ w2, const float* __restrict__ b2)
{
    __shared__ float xs[44 * 44];  // xn tile, halo 6
    __shared__ float es[34 * 34];  // e0_pre tile, halo 1

    int c = blockIdx.y, b = blockIdx.z;
    int ty0 = (blockIdx.x / (W_/TS)) * TS;
    int tx0 = (blockIdx.x % (W_/TS)) * TS;
    const float* xn = g_xn  + ((size_t)(b * C_ + c)) * HW;
    const float* ep = g_buf + ((size_t)(b * C_ + c)) * HW;

    for (int i = threadIdx.x; i < 44*44; i += 256) {
        int yy = ty0 - 6 + i / 44, xx = tx0 - 6 + i % 44;
        xs[i] = (yy >= 0 && yy < H_ && xx >= 0 && xx < W_) ? xn[yy * W_ + xx] : 0.f;
    }
    for (int i = threadIdx.x; i < 34*34; i += 256) {
        int yy = ty0 - 1 + i / 34, xx = tx0 - 1 + i % 34;
        es[i] = (yy >= 0 && yy < H_ && xx >= 0 && xx < W_) ? ep[yy * W_ + xx] : 0.f;
    }

    float k0[9], k1[9], k2[25];
    #pragma unroll
    for (int i = 0; i < 9; i++)  { k0[i] = __ldg(&w0[c*9 + i]);  k1[i] = __ldg(&w1[c*9 + i]); }
    #pragma unroll
    for (int i = 0; i < 25; i++) k2[i] = __ldg(&w2[c*25 + i]);
    float bb0 = __ldg(&b0[c]), bb1 = __ldg(&b1[c]), bb2 = __ldg(&b2[c]);
    float s0 = __ldg(&sw[b*3 + 0]), s1 = __ldg(&sw[b*3 + 1]), s2 = __ldg(&sw[b*3 + 2]);
    float pm = 1.f + __ldg(&prompt[b * C_ + c]);
    __syncthreads();

    float* out = g_xa + ((size_t)(b * C_ + c)) * HW;
    #pragma unroll
    for (int k = 0; k < 4; k++) {
        int li = threadIdx.x + k * 256;
        int py = li / TS, px = li % TS;
        // e0: 3x3 dil1 on e0_pre (center py+1,px+1 in es)
        float e0v = bb0;
        #pragma unroll
        for (int ky = 0; ky < 3; ky++)
            #pragma unroll
            for (int kx = 0; kx < 3; kx++)
                e0v += k0[ky*3 + kx] * es[(py + ky) * 34 + (px + kx)];
        // e1: 3x3 dil2 on xn (center py+6,px+6 in xs; offsets 2*(ky-1))
        float e1v = bb1;
        #pragma unroll
        for (int ky = 0; ky < 3; ky++)
            #pragma unroll
            for (int kx = 0; kx < 3; kx++)
                e1v += k1[ky*3 + kx] * xs[(py + 4 + 2*ky) * 44 + (px + 4 + 2*kx)];
        // e2: 5x5 dil3 on xn (offsets 3*(ky-2))
        float e2v = bb2;
        #pragma unroll
        for (int ky = 0; ky < 5; ky++)
            #pragma unroll
            for (int kx = 0; kx < 5; kx++)
                e2v += k2[ky*5 + kx] * xs[(py + 3*ky) * 44 + (px + 3*kx)];
        out[(ty0 + py) * W_ + (tx0 + px)] = (s0*e0v + s1*e1v + s2*e2v) * pm;
    }
}

// ---------------------------------------------------------------------------
// Kernel 3: x1 = x + proj(x_adaptive)  (96x96 matvec per pixel) -> g_buf
// ---------------------------------------------------------------------------
__global__ __launch_bounds__(256) void k_proj(
    const float* __restrict__ x,
    const float* __restrict__ w, const float* __restrict__ bias)
{
    __shared__ float ws[C_*C_];
    __shared__ float bs[C_];
    for (int i = threadIdx.x; i < (C_*C_)/4; i += 256)
        reinterpret_cast<float4*>(ws)[i] = reinterpret_cast<const float4*>(w)[i];
    if (threadIdx.x < C_) bs[threadIdx.x] = bias[threadIdx.x];
    __syncthreads();

    int b = blockIdx.y;
    int p = blockIdx.x * 256 + threadIdx.x;
    const float* ab = g_xa + (size_t)b * C_ * HW + p;
    const float* xb = x    + (size_t)b * C_ * HW + p;
    float ar[C_];
    #pragma unroll
    for (int c = 0; c < C_; c++) ar[c] = ab[(size_t)c * HW];

    float* ob = g_buf + (size_t)b * C_ * HW + p;
    #pragma unroll 1
    for (int o = 0; o < C_; o++) {
        const float4* wrow = reinterpret_cast<const float4*>(&ws[o * C_]);
        float a0 = 0.f, a1 = 0.f, a2 = 0.f, a3 = 0.f;
        #pragma unroll
        for (int c4 = 0; c4 < C_/4; c4++) {
            float4 wv = wrow[c4];
            a0 += wv.x * ar[4*c4 + 0];
            a1 += wv.y * ar[4*c4 + 1];
            a2 += wv.z * ar[4*c4 + 2];
            a3 += wv.w * ar[4*c4 + 3];
        }
        ob[(size_t)o * HW] = xb[(size_t)o * HW] + bs[o] + ((a0 + a1) + (a2 + a3));
    }
}

// ---------------------------------------------------------------------------
// Kernel 4: out = x1 + ffn2(gelu(ffn1(x1)))  — h never materialized.
// ffn2 pre-transposed in SMEM so the rank-1 update vectorizes as float4.
// ---------------------------------------------------------------------------
__global__ __launch_bounds__(256) void k_ffn(
    const float* __restrict__ w1, const float* __restrict__ b1,
    const float* __restrict__ w2, const float* __restrict__ b2,
    float* __restrict__ out)
{
    extern __shared__ float sm[];
    float* w1s = sm;                 // [192][96]
    float* w2t = sm + 2*C_*C_*2 / 2; // offset 192*96
    // (compute offsets explicitly below)
    w2t = sm + 192*C_;
    float* b1s = w2t + 192*C_;
    float* b2s = b1s + 192;

    for (int i = threadIdx.x; i < (192*C_)/4; i += 256)
        reinterpret_cast<float4*>(w1s)[i] = reinterpret_cast<const float4*>(w1)[i];
    for (int i = threadIdx.x; i < 192*C_; i += 256) {
        int o2 = i / 192, o1 = i % 192;           // w2 is [96][192]
        w2t[o1 * C_ + o2] = w2[i];
    }
    for (int i = threadIdx.x; i < 192; i += 256) b1s[i] = b1[i];
    if (threadIdx.x < C_) b2s[threadIdx.x] = b2[threadIdx.x];
    __syncthreads();

    int b = blockIdx.y;
    int p = blockIdx.x * 256 + threadIdx.x;
    const float* x1b = g_buf + (size_t)b * C_ * HW + p;

    float x1r[C_];
    #pragma unroll
    for (int c = 0; c < C_; c++) x1r[c] = x1b[(size_t)c * HW];

    float acc[C_];
    #pragma unroll
    for (int o = 0; o < C_; o++) acc[o] = x1r[o] + b2s[o];

    #pragma unroll 1
    for (int o1 = 0; o1 < 192; o1++) {
        const float4* wr = reinterpret_cast<const float4*>(&w1s[o1 * C_]);
        float a0 = 0.f, a1 = 0.f, a2 = 0.f, a3 = 0.f;
        #pragma unroll
        for (int c4 = 0; c4 < C_/4; c4++) {
            float4 wv = wr[c4];
            a0 += wv.x * x1r[4*c4 + 0];
            a1 += wv.y * x1r[4*c4 + 1];
            a2 += wv.z * x1r[4*c4 + 2];
            a3 += wv.w * x1r[4*c4 + 3];
        }
        float h = b1s[o1] + ((a0 + a1) + (a2 + a3));
        float g = h * normcdff(h);  // exact gelu
        const float4* w2r = reinterpret_cast<const float4*>(&w2t[o1 * C_]);
        #pragma unroll
        for (int o4 = 0; o4 < C_/4; o4++) {
            float4 wv = w2r[o4];
            acc[4*o4 + 0] += wv.x * g;
            acc[4*o4 + 1] += wv.y * g;
            acc[4*o4 + 2] += wv.z * g;
            acc[4*o4 + 3] += wv.w * g;
        }
    }

    float* ob = out + (size_t)b * C_ * HW + p;
    #pragma unroll
    for (int o = 0; o < C_; o++) ob[(size_t)o * HW] = acc[o];
}

// ---------------------------------------------------------------------------
extern "C" void kernel_launch(void* const* d_in, const int* in_sizes, int n_in,
                              void* d_out, int out_size)
{
    const float* x       = (const float*)d_in[0];
    const float* prompt  = (const float*)d_in[1];
    const float* sweights= (const float*)d_in[2];
    const float* ln_w    = (const float*)d_in[3];
    const float* ln_b    = (const float*)d_in[4];
    const float* e0_pw_w = (const float*)d_in[5];
    const float* e0_pw_b = (const float*)d_in[6];
    const float* e0_dw_w = (const float*)d_in[7];
    const float* e0_dw_b = (const float*)d_in[8];
    const float* e1_dw_w = (const float*)d_in[9];
    const float* e1_dw_b = (const float*)d_in[10];
    const float* e2_dw_w = (const float*)d_in[11];
    const float* e2_dw_b = (const float*)d_in[12];
    const float* proj_w  = (const float*)d_in[13];
    const float* proj_b  = (const float*)d_in[14];
    const float* ffn1_w  = (const float*)d_in[15];
    const float* ffn1_b  = (const float*)d_in[16];
    const float* ffn2_w  = (const float*)d_in[17];
    const float* ffn2_b  = (const float*)d_in[18];
    float* out = (float*)d_out;

    size_t smem_ffn = (size_t)(2 * 192 * C_ + 192 + C_) * sizeof(float);
    cudaFuncSetAttribute(k_ffn, cudaFuncAttributeMaxDynamicSharedMemorySize,
                         (int)smem_ffn);

    dim3 gpix(HW / 256, B_);
    k_ln_e0pw<<<gpix, 256>>>(x, ln_w, ln_b, e0_pw_w, e0_pw_b);

    dim3 gdw((H_/TS) * (W_/TS), C_, B_);
    k_dw<<<gdw, 256>>>(sweights, prompt,
                       e0_dw_w, e0_dw_b, e1_dw_w, e1_dw_b, e2_dw_w, e2_dw_b);

    k_proj<<<gpix, 256>>>(x, proj_w, proj_b);

    k_ffn<<<gpix, 256, smem_ffn>>>(ffn1_w, ffn1_b, ffn2_w, ffn2_b, out);
}

// round 2
// speedup vs baseline: 1.0871x; 1.0871x over previous
#include <cuda_runtime.h>
#include <cuda_bf16.h>
#include <math.h>

#define B_ 4
#define C_ 96
#define H_ 256
#define W_ 256
#define HW (H_*W_)

typedef unsigned long long u64;

// Scratch (allocation-free rule: __device__ globals)
__device__ float g_xn[B_*C_*HW];   // layernorm output
__device__ float g_buf[B_*C_*HW];  // e0_pre, later reused for x1
__device__ float g_xa[B_*C_*HW];   // x_adaptive

// ---------------- packed f32x2 helpers (Blackwell FFMA2 path) ----------------
__device__ __forceinline__ u64 fma2(u64 a, u64 b, u64 c) {
    u64 d;
    asm("fma.rn.f32x2 %0, %1, %2, %3;" : "=l"(d) : "l"(a), "l"(b), "l"(c));
    return d;
}
__device__ __forceinline__ u64 add2(u64 a, u64 b) {
    u64 d;
    asm("add.rn.f32x2 %0, %1, %2;" : "=l"(d) : "l"(a), "l"(b));
    return d;
}
__device__ __forceinline__ u64 dup2(float s) {
    u64 d; unsigned u = __float_as_uint(s);
    asm("mov.b64 %0, {%1, %1};" : "=l"(d) : "r"(u));
    return d;
}
__device__ __forceinline__ float2 unpk(u64 a) {
    unsigned lo, hi;
    asm("mov.b64 {%0, %1}, %2;" : "=r"(lo), "=r"(hi) : "l"(a));
    return make_float2(__uint_as_float(lo), __uint_as_float(hi));
}

// ---------------------------------------------------------------------------
// Core register-tiled GEMM: acc[6][4] += W[96x96] (row-major [o][k], in SMEM)
//                                      * X[96 x 128] (row k stride 128, SMEM)
// Thread (tm, tn): outputs tm*6..tm*6+5, pixels tn*8..tn*8+7 (4 f32x2 pairs).
// ---------------------------------------------------------------------------
__device__ __forceinline__ void gemm96(const float* ws, const float* xsrc,
                                       u64 acc[6][4], int tm, int tn) {
    const int ob = tm * 6;
    #pragma unroll 1
    for (int k0 = 0; k0 < 96; k0 += 4) {
        #pragma unroll
        for (int kk = 0; kk < 4; kk++) {
            const int k = k0 + kk;
            u64 xv[4];
            const u64* xr = (const u64*)(xsrc + k * 128 + tn * 8);
            xv[0] = xr[0]; xv[1] = xr[1]; xv[2] = xr[2]; xv[3] = xr[3];
            #pragma unroll
            for (int i = 0; i < 6; i++) {
                u64 wv = dup2(ws[(ob + i) * 96 + k]);
                #pragma unroll
                for (int j = 0; j < 4; j++)
                    acc[i][j] = fma2(wv, xv[j], acc[i][j]);
            }
        }
    }
}

// ---------------------------------------------------------------------------
// Kernel 1: tile LayerNorm (+ write xn) fused with e0 pointwise GEMM -> g_buf
// ---------------------------------------------------------------------------
__global__ __launch_bounds__(256, 1) void k_ln_e0pw(
    const float* __restrict__ x,
    const float* __restrict__ lnw, const float* __restrict__ lnb,
    const float* __restrict__ w,  const float* __restrict__ bias)
{
    extern __shared__ float sm[];
    float* xs  = sm;            // [96][128]
    float* ws  = sm + 12288;    // [96][96]
    float* mu  = sm + 21504;    // [128]
    float* inv = sm + 21632;    // [128]
    float* lnws= sm + 21760;    // [96]
    float* lnbs= sm + 21856;    // [96]
    float* bs  = sm + 21952;    // [96]

    const int t = threadIdx.x;
    const int b = blockIdx.y;
    const int p0 = blockIdx.x * 128;
    const float* xb = x + (size_t)b * C_ * HW + p0;

    // load x tile (rows 512B, float4 coalesced)
    for (int i = t; i < 96 * 32; i += 256) {
        int k = i >> 5, c4 = i & 31;
        ((float4*)(xs + k * 128))[c4] = ((const float4*)(xb + (size_t)k * HW))[c4];
    }
    for (int i = t; i < 9216 / 4; i += 256)
        ((float4*)ws)[i] = ((const float4*)w)[i];
    if (t < 96) { lnws[t] = lnw[t]; lnbs[t] = lnb[t]; bs[t] = bias[t]; }
    __syncthreads();

    // per-pixel stats (threads 0..127, row-wise = conflict-free)
    if (t < 128) {
        float s = 0.f, s2 = 0.f;
        #pragma unroll 8
        for (int k = 0; k < 96; k++) {
            float v = xs[k * 128 + t];
            s += v; s2 += v * v;
        }
        float m = s * (1.f / 96.f);
        float var = s2 * (1.f / 96.f) - m * m;
        mu[t] = m;
        inv[t] = rsqrtf(var + 1e-6f);
    }
    __syncthreads();

    // normalize in place + write xn
    float* xnb = g_xn + (size_t)b * C_ * HW + p0;
    for (int i = t; i < 12288; i += 256) {
        int k = i >> 7, p = i & 127;
        float v = (xs[i] - mu[p]) * inv[p] * lnws[k] + lnbs[k];
        xs[i] = v;
        xnb[(size_t)k * HW + p] = v;
    }
    __syncthreads();

    const int tm = t >> 4, tn = t & 15;
    u64 acc[6][4] = {};
    gemm96(ws, xs, acc, tm, tn);

    float* eb = g_buf + (size_t)b * C_ * HW + p0 + tn * 8;
    #pragma unroll
    for (int i = 0; i < 6; i++) {
        int o = tm * 6 + i;
        u64 b2 = dup2(bs[o]);
        #pragma unroll
        for (int j = 0; j < 4; j++)
            *(u64*)(eb + (size_t)o * HW + 2 * j) = add2(acc[i][j], b2);
    }
}

// ---------------------------------------------------------------------------
// Kernel 2: three depthwise convs + soft mixing + prompt scaling (unchanged)
// ---------------------------------------------------------------------------
#define TS 32
__global__ __launch_bounds__(256) void k_dw(
    const float* __restrict__ sw,
    const float* __restrict__ prompt,
    const float* __restrict__ w0, const float* __restrict__ b0,
    const float* __restrict__ w1, const float* __restrict__ b1,
    const float* __restrict__ w2, const float* __restrict__ b2)
{
    __shared__ float xs[44 * 44];
    __shared__ float es[34 * 34];

    int c = blockIdx.y, b = blockIdx.z;
    int ty0 = (blockIdx.x / (W_/TS)) * TS;
    int tx0 = (blockIdx.x % (W_/TS)) * TS;
    const float* xn = g_xn  + ((size_t)(b * C_ + c)) * HW;
    const float* ep = g_buf + ((size_t)(b * C_ + c)) * HW;

    for (int i = threadIdx.x; i < 44*44; i += 256) {
        int yy = ty0 - 6 + i / 44, xx = tx0 - 6 + i % 44;
        xs[i] = (yy >= 0 && yy < H_ && xx >= 0 && xx < W_) ? xn[yy * W_ + xx] : 0.f;
    }
    for (int i = threadIdx.x; i < 34*34; i += 256) {
        int yy = ty0 - 1 + i / 34, xx = tx0 - 1 + i % 34;
        es[i] = (yy >= 0 && yy < H_ && xx >= 0 && xx < W_) ? ep[yy * W_ + xx] : 0.f;
    }

    float k0[9], k1[9], k2[25];
    #pragma unroll
    for (int i = 0; i < 9; i++)  { k0[i] = __ldg(&w0[c*9 + i]);  k1[i] = __ldg(&w1[c*9 + i]); }
    #pragma unroll
    for (int i = 0; i < 25; i++) k2[i] = __ldg(&w2[c*25 + i]);
    float bb0 = __ldg(&b0[c]), bb1 = __ldg(&b1[c]), bb2 = __ldg(&b2[c]);
    float s0 = __ldg(&sw[b*3 + 0]), s1 = __ldg(&sw[b*3 + 1]), s2 = __ldg(&sw[b*3 + 2]);
    float pm = 1.f + __ldg(&prompt[b * C_ + c]);
    __syncthreads();

    float* out = g_xa + ((size_t)(b * C_ + c)) * HW;
    #pragma unroll
    for (int k = 0; k < 4; k++) {
        int li = threadIdx.x + k * 256;
        int py = li / TS, px = li % TS;
        float e0v = bb0;
        #pragma unroll
        for (int ky = 0; ky < 3; ky++)
            #pragma unroll
            for (int kx = 0; kx < 3; kx++)
                e0v += k0[ky*3 + kx] * es[(py + ky) * 34 + (px + kx)];
        float e1v = bb1;
        #pragma unroll
        for (int ky = 0; ky < 3; ky++)
            #pragma unroll
            for (int kx = 0; kx < 3; kx++)
                e1v += k1[ky*3 + kx] * xs[(py + 4 + 2*ky) * 44 + (px + 4 + 2*kx)];
        float e2v = bb2;
        #pragma unroll
        for (int ky = 0; ky < 5; ky++)
            #pragma unroll
            for (int kx = 0; kx < 5; kx++)
                e2v += k2[ky*5 + kx] * xs[(py + 3*ky) * 44 + (px + 3*kx)];
        out[(ty0 + py) * W_ + (tx0 + px)] = (s0*e0v + s1*e1v + s2*e2v) * pm;
    }
}

// ---------------------------------------------------------------------------
// Kernel 3: x1 = x + proj(x_adaptive) -> g_buf  (tiled GEMM + residual)
// ---------------------------------------------------------------------------
__global__ __launch_bounds__(256, 1) void k_proj(
    const float* __restrict__ x,
    const float* __restrict__ w, const float* __restrict__ bias)
{
    extern __shared__ float sm[];
    float* xs = sm;          // [96][128] x_adaptive tile
    float* ws = sm + 12288;  // [96][96]
    float* bs = sm + 21504;  // [96]

    const int t = threadIdx.x;
    const int b = blockIdx.y;
    const int p0 = blockIdx.x * 128;
    const float* ab = g_xa + (size_t)b * C_ * HW + p0;

    for (int i = t; i < 96 * 32; i += 256) {
        int k = i >> 5, c4 = i & 31;
        ((float4*)(xs + k * 128))[c4] = ((const float4*)(ab + (size_t)k * HW))[c4];
    }
    for (int i = t; i < 9216 / 4; i += 256)
        ((float4*)ws)[i] = ((const float4*)w)[i];
    if (t < 96) bs[t] = bias[t];
    __syncthreads();

    const int tm = t >> 4, tn = t & 15;
    u64 acc[6][4] = {};
    gemm96(ws, xs, acc, tm, tn);

    const float* rb = x + (size_t)b * C_ * HW + p0 + tn * 8;
    float* ob = g_buf + (size_t)b * C_ * HW + p0 + tn * 8;
    #pragma unroll
    for (int i = 0; i < 6; i++) {
        int o = tm * 6 + i;
        u64 b2 = dup2(bs[o]);
        #pragma unroll
        for (int j = 0; j < 4; j++) {
            u64 res = *(const u64*)(rb + (size_t)o * HW + 2 * j);
            *(u64*)(ob + (size_t)o * HW + 2 * j) = add2(add2(acc[i][j], b2), res);
        }
    }
}

// ---------------------------------------------------------------------------
// Kernel 4: out = x1 + ffn2(gelu(ffn1(x1))) — fused, h tile lives in SMEM
// ---------------------------------------------------------------------------
__global__ __launch_bounds__(256, 1) void k_ffn(
    const float* __restrict__ w1, const float* __restrict__ b1,
    const float* __restrict__ w2, const float* __restrict__ b2,
    float* __restrict__ out)
{
    extern __shared__ float sm[];
    float* xs  = sm;            // [96][128] x1 tile (kept for residual)
    float* hs  = sm + 12288;    // [192][128] gelu(ffn1) tile
    float* ws  = sm + 36864;    // [96][96] current weight chunk
    float* b1s = sm + 46080;    // [192]
    float* b2s = sm + 46272;    // [96]

    const int t = threadIdx.x;
    const int b = blockIdx.y;
    const int p0 = blockIdx.x * 128;
    const float* x1b = g_buf + (size_t)b * C_ * HW + p0;

    for (int i = t; i < 96 * 32; i += 256) {
        int k = i >> 5, c4 = i & 31;
        ((float4*)(xs + k * 128))[c4] = ((const float4*)(x1b + (size_t)k * HW))[c4];
    }
    if (t < 192) b1s[t] = b1[t];
    if (t < 96)  b2s[t] = b2[t];

    const int tm = t >> 4, tn = t & 15;

    // ---- GEMM1: h = gelu(w1 @ x1 + b1), two 96-output chunks ----
    #pragma unroll 1
    for (int oc = 0; oc < 2; oc++) {
        __syncthreads();   // xs/b1s ready (oc=0); prior ws readers done (oc=1)
        for (int i = t; i < 9216 / 4; i += 256)
            ((float4*)ws)[i] = ((const float4*)(w1 + oc * 9216))[i];
        __syncthreads();

        u64 acc[6][4] = {};
        gemm96(ws, xs, acc, tm, tn);

        #pragma unroll
        for (int i = 0; i < 6; i++) {
            int o = oc * 96 + tm * 6 + i;
            float bb = b1s[o];
            #pragma unroll
            for (int j = 0; j < 4; j++) {
                float2 v = unpk(acc[i][j]);
                float h0 = v.x + bb, h1 = v.y + bb;
                float g0 = h0 * normcdff(h0);
                float g1 = h1 * normcdff(h1);
                *(float2*)(hs + o * 128 + tn * 8 + 2 * j) = make_float2(g0, g1);
            }
        }
    }

    // ---- GEMM2: out = x1 + w2 @ h + b2, K=192 in two chunks ----
    u64 acc2[6][4] = {};
    #pragma unroll 1
    for (int kc = 0; kc < 2; kc++) {
        __syncthreads();   // hs writes done / prior ws readers done
        for (int i = t; i < 9216; i += 256)
            ws[i] = w2[(i / 96) * 192 + kc * 96 + (i % 96)];
        __syncthreads();
        gemm96(ws, hs + kc * 96 * 128, acc2, tm, tn);
    }

    float* ob = out + (size_t)b * C_ * HW + p0 + tn * 8;
    #pragma unroll
    for (int i = 0; i < 6; i++) {
        int o = tm * 6 + i;
        u64 bp = dup2(b2s[o]);
        #pragma unroll
        for (int j = 0; j < 4; j++) {
            u64 x1v = *(const u64*)(xs + o * 128 + tn * 8 + 2 * j);
            *(u64*)(ob + (size_t)o * HW + 2 * j) = add2(add2(acc2[i][j], bp), x1v);
        }
    }
}

// ---------------------------------------------------------------------------
extern "C" void kernel_launch(void* const* d_in, const int* in_sizes, int n_in,
                              void* d_out, int out_size)
{
    const float* x       = (const float*)d_in[0];
    const float* prompt  = (const float*)d_in[1];
    const float* sweights= (const float*)d_in[2];
    const float* ln_w    = (const float*)d_in[3];
    const float* ln_b    = (const float*)d_in[4];
    const float* e0_pw_w = (const float*)d_in[5];
    const float* e0_pw_b = (const float*)d_in[6];
    const float* e0_dw_w = (const float*)d_in[7];
    const float* e0_dw_b = (const float*)d_in[8];
    const float* e1_dw_w = (const float*)d_in[9];
    const float* e1_dw_b = (const float*)d_in[10];
    const float* e2_dw_w = (const float*)d_in[11];
    const float* e2_dw_b = (const float*)d_in[12];
    const float* proj_w  = (const float*)d_in[13];
    const float* proj_b  = (const float*)d_in[14];
    const float* ffn1_w  = (const float*)d_in[15];
    const float* ffn1_b  = (const float*)d_in[16];
    const float* ffn2_w  = (const float*)d_in[17];
    const float* ffn2_b  = (const float*)d_in[18];
    float* out = (float*)d_out;

    static int attr_done = 0;
    // (setting attributes every call is harmless and keeps launch deterministic)
    cudaFuncSetAttribute(k_ln_e0pw, cudaFuncAttributeMaxDynamicSharedMemorySize, 22048 * 4);
    cudaFuncSetAttribute(k_proj,    cudaFuncAttributeMaxDynamicSharedMemorySize, 21600 * 4);
    cudaFuncSetAttribute(k_ffn,     cudaFuncAttributeMaxDynamicSharedMemorySize, 46368 * 4);
    (void)attr_done;

    dim3 gg(HW / 128, B_);

    k_ln_e0pw<<<gg, 256, 22048 * 4>>>(x, ln_w, ln_b, e0_pw_w, e0_pw_b);

    dim3 gdw((H_/TS) * (W_/TS), C_, B_);
    k_dw<<<gdw, 256>>>(sweights, prompt,
                       e0_dw_w, e0_dw_b, e1_dw_w, e1_dw_b, e2_dw_w, e2_dw_b);

    k_proj<<<gg, 256, 21600 * 4>>>(x, proj_w, proj_b);

    k_ffn<<<gg, 256, 46368 * 4>>>(ffn1_w, ffn1_b, ffn2_w, ffn2_b, out);
}